// round 1
// baseline (speedup 1.0000x reference)
#include <cuda_runtime.h>
#include <cstdint>

// Packed f32x2 helpers (Blackwell sm_100+). FFMA2 only reachable via PTX.
__device__ __forceinline__ unsigned long long pack2(float lo, float hi) {
    unsigned long long r;
    asm("mov.b64 %0, {%1, %2};" : "=l"(r) : "f"(lo), "f"(hi));
    return r;
}
__device__ __forceinline__ void unpack2(unsigned long long v, float& lo, float& hi) {
    asm("mov.b64 {%0, %1}, %2;" : "=f"(lo), "=f"(hi) : "l"(v));
}
__device__ __forceinline__ unsigned long long fma2(unsigned long long a,
                                                   unsigned long long b,
                                                   unsigned long long c) {
    unsigned long long d;
    asm("fma.rn.f32x2 %0, %1, %2, %3;" : "=l"(d) : "l"(a), "l"(b), "l"(c));
    return d;
}
__device__ __forceinline__ unsigned long long mul2(unsigned long long a,
                                                   unsigned long long b) {
    unsigned long long d;
    asm("mul.rn.f32x2 %0, %1, %2;" : "=l"(d) : "l"(a), "l"(b));
    return d;
}
__device__ __forceinline__ float tanh_approx(float x) {
    float y;
    asm("tanh.approx.f32 %0, %1;" : "=f"(y) : "f"(x));
    return y;
}
__device__ __forceinline__ unsigned long long tanh2(unsigned long long v) {
    float lo, hi;
    unpack2(v, lo, hi);
    return pack2(tanh_approx(lo), tanh_approx(hi));
}
// sigmoid(x) = 0.5 + 0.5*tanh(0.5*x)  -> single MUFU per value
__device__ __forceinline__ float sigmoid_fast(float x) {
    return fmaf(0.5f, tanh_approx(0.5f * x), 0.5f);
}

// Each thread processes a PAIR of adjacent pixels, packed lane-wise into f32x2.
// Hidden 8x8 weight is duplicated-packed (w,w) and register-resident; in/out
// layers are scalar to keep register count under 255.
__global__ void __launch_bounds__(256, 1)
mlp_field_kernel(const float4* __restrict__ x4,
                 const float* __restrict__ W_in,
                 const float* __restrict__ W_h,
                 const float* __restrict__ W_out,
                 float2* __restrict__ out2,
                 int npairs)
{
    // Weight setup, amortized over the grid-stride loop (uniform broadcast LDGs).
    float win[16];
#pragma unroll
    for (int i = 0; i < 16; i++) win[i] = __ldg(W_in + i);

    unsigned long long wh[64];
#pragma unroll
    for (int i = 0; i < 64; i++) {
        float w = __ldg(W_h + i);
        wh[i] = pack2(w, w);
    }

    float wout[24];
#pragma unroll
    for (int i = 0; i < 24; i++) wout[i] = __ldg(W_out + i);

    const int stride = gridDim.x * blockDim.x;
    for (int p = blockIdx.x * blockDim.x + threadIdx.x; p < npairs; p += stride) {
        float4 xy = x4[p];  // (x0, y0, x1, y1): two adjacent pixels, coalesced 16B

        // ---- input layer (scalar, 2 pixels), pack result ----
        unsigned long long h[8];
#pragma unroll
        for (int j = 0; j < 8; j++) {
            float a0 = fmaf(win[2 * j], xy.x, win[2 * j + 1] * xy.y);
            float a1 = fmaf(win[2 * j], xy.z, win[2 * j + 1] * xy.w);
            h[j] = pack2(tanh_approx(a0), tanh_approx(a1));
        }

        // ---- 4 shared-weight hidden layers, fully packed f32x2 ----
#pragma unroll
        for (int l = 0; l < 4; l++) {
            unsigned long long nh[8];
#pragma unroll
            for (int j = 0; j < 8; j++) {
                unsigned long long acc = mul2(wh[8 * j + 0], h[0]);
#pragma unroll
                for (int k = 1; k < 8; k++)
                    acc = fma2(wh[8 * j + k], h[k], acc);
                nh[j] = tanh2(acc);
            }
#pragma unroll
            for (int j = 0; j < 8; j++) h[j] = nh[j];
        }

        // ---- output layer (scalar per pixel) + fast sigmoid ----
        float h0[8], h1[8];
#pragma unroll
        for (int j = 0; j < 8; j++) unpack2(h[j], h0[j], h1[j]);

        float o0[3], o1[3];
#pragma unroll
        for (int o = 0; o < 3; o++) {
            float a0 = wout[8 * o] * h0[0];
            float a1 = wout[8 * o] * h1[0];
#pragma unroll
            for (int k = 1; k < 8; k++) {
                a0 = fmaf(wout[8 * o + k], h0[k], a0);
                a1 = fmaf(wout[8 * o + k], h1[k], a1);
            }
            o0[o] = sigmoid_fast(a0);
            o1[o] = sigmoid_fast(a1);
        }

        // 6 contiguous floats per pair -> three 8B stores (all 8B-aligned)
        float2* dst = out2 + 3ull * (unsigned long long)p;
        dst[0] = make_float2(o0[0], o0[1]);
        dst[1] = make_float2(o0[2], o1[0]);
        dst[2] = make_float2(o1[1], o1[2]);
    }
}

extern "C" void kernel_launch(void* const* d_in, const int* in_sizes, int n_in,
                              void* d_out, int out_size)
{
    const float* x     = (const float*)d_in[0];  // [N, 2]
    const float* W_in  = (const float*)d_in[1];  // [8, 2]
    const float* W_h   = (const float*)d_in[2];  // [8, 8]
    const float* W_out = (const float*)d_in[3];  // [3, 8]

    int n_pixels = in_sizes[0] / 2;
    int npairs = n_pixels / 2;  // N = 16777216, divisible by 4

    const int threads = 256;
    const int blocks = 1216;  // 152 SMs * 8 waves of one 8-warp block each
    mlp_field_kernel<<<blocks, threads>>>((const float4*)x, W_in, W_h, W_out,
                                          (float2*)d_out, npairs);
}

// round 3
// speedup vs baseline: 1.5120x; 1.5120x over previous
#include <cuda_runtime.h>
#include <cuda_fp16.h>

__device__ __forceinline__ __half2 tanh_h2(__half2 v) {
    unsigned int uv, ur;
    memcpy(&uv, &v, 4);
    asm("tanh.approx.f16x2 %0, %1;" : "=r"(ur) : "r"(uv));
    __half2 r;
    memcpy(&r, &ur, 4);
    return r;
}
__device__ __forceinline__ float tanh_f32(float x) {
    float y;
    asm("tanh.approx.f32 %0, %1;" : "=f"(y) : "f"(x));
    return y;
}
// sigmoid(x) = 0.5 + 0.5*tanh(0.5*x) -> single MUFU, fp32 for final accuracy
__device__ __forceinline__ float sigmoid_fast(float x) {
    return fmaf(0.5f, tanh_f32(0.5f * x), 0.5f);
}

// Two pixels per thread, packed lane-wise into half2 (px0, px1).
// All matmuls in HFMA2; all tanh in tanh.approx.f16x2; final sigmoid in fp32.
// Weight footprint: wh 64 regs (vs 128 in fp32x2) -> much higher occupancy.
__global__ void __launch_bounds__(128, 3)
mlp_field_kernel(const float4* __restrict__ x4,
                 const float* __restrict__ W_in,
                 const float* __restrict__ W_h,
                 const float* __restrict__ W_out,
                 float2* __restrict__ out2,
                 int npairs)
{
    // Duplicated-packed weights (w, w) as half2 — register resident,
    // amortized over the grid-stride loop.
    __half2 winx[8], winy[8];
#pragma unroll
    for (int j = 0; j < 8; j++) {
        winx[j] = __float2half2_rn(__ldg(W_in + 2 * j));
        winy[j] = __float2half2_rn(__ldg(W_in + 2 * j + 1));
    }
    __half2 wh[64];
#pragma unroll
    for (int i = 0; i < 64; i++) wh[i] = __float2half2_rn(__ldg(W_h + i));
    __half2 wout[24];
#pragma unroll
    for (int i = 0; i < 24; i++) wout[i] = __float2half2_rn(__ldg(W_out + i));

    const int stride = gridDim.x * blockDim.x;
    for (int p = blockIdx.x * blockDim.x + threadIdx.x; p < npairs; p += stride) {
        float4 xy = __ldg(x4 + p);  // (x0, y0, x1, y1): two adjacent pixels

        // pack coords as (px0, px1)
        __half2 xv = __floats2half2_rn(xy.x, xy.z);
        __half2 yv = __floats2half2_rn(xy.y, xy.w);

        // ---- input layer: 2 HFMA-class ops + 1 f16x2 tanh per neuron ----
        __half2 h[8];
#pragma unroll
        for (int j = 0; j < 8; j++)
            h[j] = tanh_h2(__hfma2(winy[j], yv, __hmul2(winx[j], xv)));

        // ---- 4 shared-weight hidden layers, fully half2 ----
#pragma unroll
        for (int l = 0; l < 4; l++) {
            __half2 nh[8];
#pragma unroll
            for (int j = 0; j < 8; j++) {
                __half2 acc = __hmul2(wh[8 * j + 0], h[0]);
#pragma unroll
                for (int k = 1; k < 8; k++)
                    acc = __hfma2(wh[8 * j + k], h[k], acc);
                nh[j] = tanh_h2(acc);
            }
#pragma unroll
            for (int j = 0; j < 8; j++) h[j] = nh[j];
        }

        // ---- output layer in half2, sigmoid in fp32 ----
        float o0[3], o1[3];
#pragma unroll
        for (int o = 0; o < 3; o++) {
            __half2 acc = __hmul2(wout[8 * o + 0], h[0]);
#pragma unroll
            for (int k = 1; k < 8; k++)
                acc = __hfma2(wout[8 * o + k], h[k], acc);
            float2 a = __half22float2(acc);
            o0[o] = sigmoid_fast(a.x);
            o1[o] = sigmoid_fast(a.y);
        }

        // 6 contiguous floats per pair -> three 8B stores
        float2* dst = out2 + 3ull * (unsigned long long)p;
        dst[0] = make_float2(o0[0], o0[1]);
        dst[1] = make_float2(o0[2], o1[0]);
        dst[2] = make_float2(o1[1], o1[2]);
    }
}

extern "C" void kernel_launch(void* const* d_in, const int* in_sizes, int n_in,
                              void* d_out, int out_size)
{
    const float* x     = (const float*)d_in[0];  // [N, 2]
    const float* W_in  = (const float*)d_in[1];  // [8, 2]
    const float* W_h   = (const float*)d_in[2];  // [8, 8]
    const float* W_out = (const float*)d_in[3];  // [3, 8]

    int n_pixels = in_sizes[0] / 2;
    int npairs = n_pixels / 2;  // N = 16777216, divisible by 4

    const int threads = 128;
    const int blocks = 1824;  // grid-stride, ~12 blocks/SM of work
    mlp_field_kernel<<<blocks, threads>>>((const float4*)x, W_in, W_h, W_out,
                                          (float2*)d_out, npairs);
}